// round 11
// baseline (speedup 1.0000x reference)
#include <cuda_runtime.h>
#include <math.h>

#define BB 16      // batch
#define TT 1024    // sequence
#define JJ 128     // input dim
#define HH 64      // hidden (complex) dim
#define NSEG 16    // t-segments per batch (64 t each)

// Per-(b, segment) ZERO-STATE carry C (complex, 64 h).
__device__ __align__(16) float2 g_C[BB * NSEG * HH];
// lam^k table, k = 1..64:  g_L[(k-1)*64 + h]
__device__ __align__(16) float2 g_L[64 * HH];
// Incoming segment state S per (b, seg, h).
__device__ __align__(16) float2 g_S[BB * NSEG * HH];

// ---------------------------------------------------------------------------
// tf32 helpers
// ---------------------------------------------------------------------------
__device__ __forceinline__ unsigned tf32bits(float v) {
    unsigned r;
    asm("cvt.rna.tf32.f32 %0, %1;" : "=r"(r) : "f"(v));
    return r;
}
__device__ __forceinline__ void mma_tf32(float& d0, float& d1, float& d2, float& d3,
                                         unsigned a0, unsigned a1, unsigned a2, unsigned a3,
                                         unsigned b0, unsigned b1) {
    asm("mma.sync.aligned.m16n8k8.row.col.f32.tf32.tf32.f32 "
        "{%0,%1,%2,%3}, {%4,%5,%6,%7}, {%8,%9}, {%0,%1,%2,%3};"
        : "+f"(d0), "+f"(d1), "+f"(d2), "+f"(d3)
        : "r"(a0), "r"(a1), "r"(a2), "r"(a3), "r"(b0), "r"(b1));
}
__device__ __forceinline__ unsigned fbits(float v) { return __float_as_uint(v); }

// ---------------------------------------------------------------------------
// K1: fused GEMM (3xTF32) + zero-state segment scan.  (round-9 warp code,
// half-size blocks: 64t x 64h, 256 blocks, 2 blocks/SM -> 4 warps/SMSP)
// Grid 256 = 16 b x 16 t-segments (64 t each), 256 threads.
// ---------------------------------------------------------------------------
#define KST 68
#define K1_SMEM_BYTES (256 * KST * 4)   // xhi(64)+xlo(64)+bhi(64)+blo(64) rows

__global__ __launch_bounds__(256) void fused_kernel(const float* __restrict__ x,
                                                    const float* __restrict__ Bm,
                                                    const float* __restrict__ nu,
                                                    const float* __restrict__ theta,
                                                    float* __restrict__ out) {
    extern __shared__ __align__(16) float sm[];
    float* xhi = sm;                    // [t 0..63][j 0..63] stride 68
    float* xlo = sm + 64 * KST;
    float* bhi = sm + 128 * KST;        // [h 0..63][j 0..63] stride 68
    float* blo = sm + 192 * KST;

    __shared__ float Vr_s[4 * 64], Vi_s[4 * 64];
    __shared__ float Wr_s[4 * 64], Wi_s[4 * 64];

    const int tid  = threadIdx.x;
    const int lane = tid & 31;
    const int wid  = tid >> 5;
    const int wt   = wid >> 1;          // 0..1 -> 32 t
    const int wh   = wid & 1;           // 0..1 -> 32 h
    const int b    = blockIdx.x >> 4;
    const int ts   = blockIdx.x & 15;
    const int t0   = ts * 64;
    const int lr   = lane >> 2;         // 0..7
    const int lc   = lane & 3;          // 0..3

    float acc[2][4][4];
#pragma unroll
    for (int m = 0; m < 2; ++m)
#pragma unroll
        for (int n = 0; n < 4; ++n)
#pragma unroll
            for (int q = 0; q < 4; ++q) acc[m][n][q] = 0.f;

    const float4* x4 = reinterpret_cast<const float4*>(x);
    const float4* B4 = reinterpret_cast<const float4*>(Bm);

    for (int kc = 0; kc < 2; ++kc) {
        if (kc) __syncthreads();
        // Stage x chunk: 64 t x 16 float4, tf32 hi/lo split
#pragma unroll
        for (int i = 0; i < 4; ++i) {
            int f  = tid + 256 * i;
            int t  = f >> 4;
            int jq = f & 15;
            float4 v = x4[(b * TT + t0 + t) * 32 + kc * 16 + jq];
            float4 hv, lv;
            hv.x = __uint_as_float(tf32bits(v.x)); lv.x = v.x - hv.x;
            hv.y = __uint_as_float(tf32bits(v.y)); lv.y = v.y - hv.y;
            hv.z = __uint_as_float(tf32bits(v.z)); lv.z = v.z - hv.z;
            hv.w = __uint_as_float(tf32bits(v.w)); lv.w = v.w - hv.w;
            *reinterpret_cast<float4*>(&xhi[t * KST + jq * 4]) = hv;
            *reinterpret_cast<float4*>(&xlo[t * KST + jq * 4]) = lv;
        }
        // Stage B chunk: 64 h x 16 float4
#pragma unroll
        for (int i = 0; i < 4; ++i) {
            int f  = tid + 256 * i;
            int h  = f >> 4;
            int jq = f & 15;
            float4 v = B4[h * 32 + kc * 16 + jq];
            float4 hv, lv;
            hv.x = __uint_as_float(tf32bits(v.x)); lv.x = v.x - hv.x;
            hv.y = __uint_as_float(tf32bits(v.y)); lv.y = v.y - hv.y;
            hv.z = __uint_as_float(tf32bits(v.z)); lv.z = v.z - hv.z;
            hv.w = __uint_as_float(tf32bits(v.w)); lv.w = v.w - hv.w;
            *reinterpret_cast<float4*>(&bhi[h * KST + jq * 4]) = hv;
            *reinterpret_cast<float4*>(&blo[h * KST + jq * 4]) = lv;
        }
        __syncthreads();

#pragma unroll
        for (int ks = 0; ks < 8; ++ks) {
            const int j0 = ks * 8;
            unsigned ah[2][4], al[2][4];
#pragma unroll
            for (int m = 0; m < 2; ++m) {
                int base = (wt * 32 + m * 16 + lr) * KST + j0 + lc;
                ah[m][0] = fbits(xhi[base]);
                ah[m][1] = fbits(xhi[base + 8 * KST]);
                ah[m][2] = fbits(xhi[base + 4]);
                ah[m][3] = fbits(xhi[base + 8 * KST + 4]);
                al[m][0] = fbits(xlo[base]);
                al[m][1] = fbits(xlo[base + 8 * KST]);
                al[m][2] = fbits(xlo[base + 4]);
                al[m][3] = fbits(xlo[base + 8 * KST + 4]);
            }
#pragma unroll
            for (int n = 0; n < 4; ++n) {
                int hb = (wh * 32 + n * 8 + lr) * KST + j0 + lc;
                unsigned bh0 = fbits(bhi[hb]);
                unsigned bh1 = fbits(bhi[hb + 4]);
                unsigned bl0 = fbits(blo[hb]);
                unsigned bl1 = fbits(blo[hb + 4]);
#pragma unroll
                for (int m = 0; m < 2; ++m) {
                    mma_tf32(acc[m][n][0], acc[m][n][1], acc[m][n][2], acc[m][n][3],
                             ah[m][0], ah[m][1], ah[m][2], ah[m][3], bh0, bh1);
                    mma_tf32(acc[m][n][0], acc[m][n][1], acc[m][n][2], acc[m][n][3],
                             ah[m][0], ah[m][1], ah[m][2], ah[m][3], bl0, bl1);
                    mma_tf32(acc[m][n][0], acc[m][n][1], acc[m][n][2], acc[m][n][3],
                             al[m][0], al[m][1], al[m][2], al[m][3], bh0, bh1);
                }
            }
        }
    }
    __syncthreads();

    // Stage D = Bx into smem as [t][h], stride 65 (aliases staging region).
    float* sD = sm;   // 64 * 65 floats
#pragma unroll
    for (int m = 0; m < 2; ++m)
#pragma unroll
        for (int n = 0; n < 4; ++n) {
            int tr = wt * 32 + m * 16 + lr;
            int hc = wh * 32 + n * 8 + 2 * lc;
            sD[tr * 65 + hc]           = acc[m][n][0];
            sD[tr * 65 + hc + 1]       = acc[m][n][1];
            sD[(tr + 8) * 65 + hc]     = acc[m][n][2];
            sD[(tr + 8) * 65 + hc + 1] = acc[m][n][3];
        }
    __syncthreads();

    // ---- Segment-local scan (zero initial state): 4 chunks of 16 t ----
    const int h = tid & 63;
    const int c = tid >> 6;             // 0..3

    const float mag = expf(-expf(nu[h]));
    float sn, cs;
    sincosf(theta[h], &sn, &cs);
    const float Lr = mag * cs;
    const float Li = mag * sn;

    // P = lam^16
    float Pr = Lr, Pi = Li;
#pragma unroll
    for (int s = 0; s < 4; ++s) {
        float nr = Pr * Pr - Pi * Pi;
        float ni = 2.f * Pr * Pi;
        Pr = nr; Pi = ni;
    }

    float u[16];
#pragma unroll
    for (int k = 0; k < 16; ++k) u[k] = sD[(c * 16 + k) * 65 + h];

    // Phase A: local chunk scan from zero -> chunk value V
    float yr = 0.f, yi = 0.f;
#pragma unroll
    for (int k = 0; k < 16; ++k) {
        float nyr = fmaf(Lr, yr, fmaf(-Li, yi, u[k]));
        float nyi = fmaf(Lr, yi, Li * yr);
        yr = nyr; yi = nyi;
    }
    Vr_s[c * 64 + h] = yr;
    Vi_s[c * 64 + h] = yi;
    __syncthreads();

    // Combine (tid<64): chunk prefixes + segment carry -> g_C.
    if (tid < 64) {
        float wr = 0.f, wi = 0.f;
        Wr_s[h] = 0.f; Wi_s[h] = 0.f;
#pragma unroll
        for (int cc = 1; cc < 4; ++cc) {
            float vr = Vr_s[(cc - 1) * 64 + h];
            float vi = Vi_s[(cc - 1) * 64 + h];
            float nwr = vr + (Pr * wr - Pi * wi);
            float nwi = vi + (Pr * wi + Pi * wr);
            wr = nwr; wi = nwi;
            Wr_s[cc * 64 + h] = wr;
            Wi_s[cc * 64 + h] = wi;
        }
        float vr = Vr_s[3 * 64 + h];
        float vi = Vi_s[3 * 64 + h];
        float Cr = vr + (Pr * wr - Pi * wi);
        float Ci = vi + (Pr * wi + Pi * wr);
        g_C[(b * NSEG + ts) * 64 + h] = make_float2(Cr, Ci);
    }
    __syncthreads();

    // Phase C: zero-state outputs (fixup adds the cross-segment correction).
    yr = Wr_s[c * 64 + h];
    yi = Wi_s[c * 64 + h];
    float* op = out + (b * TT + t0 + c * 16) * (2 * HH) + h;
#pragma unroll
    for (int k = 0; k < 16; ++k) {
        float nyr = fmaf(Lr, yr, fmaf(-Li, yi, u[k]));
        float nyi = fmaf(Lr, yi, Li * yr);
        yr = nyr; yi = nyi;
        op[k * 128]      = yr;   // re at [b,t,h]
        op[k * 128 + 64] = yi;   // im at [b,t,H+h]
    }
}

// ---------------------------------------------------------------------------
// Prep: lam^k table (k=1..64) + incoming states S (16 segments/b).
// 128 blocks x 128 threads = 16384 threads: one per (b,seg,h) state.
// Horner over <=15 carries: predicated-unrolled loads (MLP ~15), then
// a short predicated FMA chain.
// ---------------------------------------------------------------------------
__global__ __launch_bounds__(128) void prep_kernel(const float* __restrict__ nu,
                                                   const float* __restrict__ theta) {
    const int gid = blockIdx.x * 128 + threadIdx.x;   // 0..16383
    const int h   = gid & 63;
    const int idx = gid >> 6;                         // 0..255
    const int b   = idx >> 4;
    const int seg = idx & 15;

    const float enu = expf(nu[h]);
    const float th  = theta[h];

    // Table entry lam^(idx+1) for idx < 64
    if (idx < 64) {
        int kk = idx + 1;
        float m = expf(-(float)kk * enu);
        float s, c;
        sincosf((float)kk * th, &s, &c);
        g_L[(kk - 1) * 64 + h] = make_float2(m * c, m * s);
    }

    // Q = lam^64
    float mq = expf(-64.f * enu);
    float sq, cq;
    sincosf(64.f * th, &sq, &cq);
    const float Qr = mq * cq, Qi = mq * sq;

    // Gather predecessor carries with independent (predicated) loads.
    float2 cg[15];
#pragma unroll
    for (int g = 0; g < 15; ++g)
        cg[g] = (g < seg) ? g_C[(b * NSEG + g) * 64 + h] : make_float2(0.f, 0.f);

    float Sr = 1.f, Si = 0.f;
#pragma unroll
    for (int g = 0; g < 15; ++g) {
        if (g < seg) {
            float nr = Qr * Sr - Qi * Si + cg[g].x;
            float ni = Qr * Si + Qi * Sr + cg[g].y;
            Sr = nr; Si = ni;
        }
    }
    g_S[(b * NSEG + seg) * 64 + h] = make_float2(Sr, Si);
}

// ---------------------------------------------------------------------------
// Fixup: out[b,t,h] += lam_h^(tl+1) * S(b,seg,h).  Chain-free table loads.
// 512 blocks x 256 threads, 2 t per thread (more resident warps on the RMW).
// ---------------------------------------------------------------------------
__global__ __launch_bounds__(256) void fixup_kernel(float* __restrict__ out) {
    const int tid = threadIdx.x;
    const int bx  = blockIdx.x;         // 0..511
    const int b   = bx >> 5;
    const int tb  = bx & 31;            // 32-t block
    const int tt  = tid >> 4;           // 0..15
    const int hq  = tid & 15;
    const int h0  = hq * 4;
    const int t0  = tb * 32 + tt * 2;   // 2 consecutive t, same segment
    const int seg = t0 >> 6;

    const float4* Sp =
        reinterpret_cast<const float4*>(&g_S[(b * NSEG + seg) * 64 + h0]);
    float4 s01 = Sp[0], s23 = Sp[1];
    const float Sr[4] = {s01.x, s01.z, s23.x, s23.z};
    const float Si[4] = {s01.y, s01.w, s23.y, s23.w};

#pragma unroll
    for (int i = 0; i < 2; ++i) {
        const int t = t0 + i;
        const int k = (t & 63) + 1;
        const float4* Lp = reinterpret_cast<const float4*>(&g_L[(k - 1) * 64 + h0]);
        float4 l01 = Lp[0], l23 = Lp[1];
        float lkr[4] = {l01.x, l01.z, l23.x, l23.z};
        float lki[4] = {l01.y, l01.w, l23.y, l23.w};

        float* p = out + (b * TT + t) * (2 * HH) + h0;
        float4 re = *reinterpret_cast<float4*>(p);
        float4 im = *reinterpret_cast<float4*>(p + 64);
        re.x += lkr[0] * Sr[0] - lki[0] * Si[0];
        re.y += lkr[1] * Sr[1] - lki[1] * Si[1];
        re.z += lkr[2] * Sr[2] - lki[2] * Si[2];
        re.w += lkr[3] * Sr[3] - lki[3] * Si[3];
        im.x += lkr[0] * Si[0] + lki[0] * Sr[0];
        im.y += lkr[1] * Si[1] + lki[1] * Sr[1];
        im.z += lkr[2] * Si[2] + lki[2] * Sr[2];
        im.w += lkr[3] * Si[3] + lki[3] * Sr[3];
        *reinterpret_cast<float4*>(p)      = re;
        *reinterpret_cast<float4*>(p + 64) = im;
    }
}

// ---------------------------------------------------------------------------
extern "C" void kernel_launch(void* const* d_in, const int* in_sizes, int n_in,
                              void* d_out, int out_size) {
    const float* x     = (const float*)d_in[0];   // [16,1024,128]
    const float* Bm    = (const float*)d_in[1];   // [64,128]
    const float* nu    = (const float*)d_in[2];   // [64]
    const float* theta = (const float*)d_in[3];   // [64]
    float* out = (float*)d_out;                   // [16,1024,128]

    cudaFuncSetAttribute(fused_kernel,
                         cudaFuncAttributeMaxDynamicSharedMemorySize,
                         K1_SMEM_BYTES);
    fused_kernel<<<256, 256, K1_SMEM_BYTES>>>(x, Bm, nu, theta, out);
    prep_kernel<<<128, 128>>>(nu, theta);
    fixup_kernel<<<512, 256>>>(out);
}

// round 12
// speedup vs baseline: 1.2166x; 1.2166x over previous
#include <cuda_runtime.h>
#include <math.h>

#define BB 16      // batch
#define TT 1024    // sequence
#define JJ 128     // input dim
#define HH 64      // hidden (complex) dim

// Per-(b, segment) ZERO-STATE carry C (complex, 64 h).
__device__ __align__(16) float2 g_C[BB * 8 * HH];
// lam^k table, k = 1..128:  g_L[(k-1)*64 + h]
__device__ __align__(16) float2 g_L[128 * HH];
// Incoming segment state S per (b, seg, h).
__device__ __align__(16) float2 g_S[BB * 8 * HH];

// ---------------------------------------------------------------------------
// helpers
// ---------------------------------------------------------------------------
__device__ __forceinline__ unsigned tf32bits(float v) {
    unsigned r;
    asm("cvt.rna.tf32.f32 %0, %1;" : "=r"(r) : "f"(v));
    return r;
}
__device__ __forceinline__ void mma_tf32(float& d0, float& d1, float& d2, float& d3,
                                         unsigned a0, unsigned a1, unsigned a2, unsigned a3,
                                         unsigned b0, unsigned b1) {
    asm("mma.sync.aligned.m16n8k8.row.col.f32.tf32.tf32.f32 "
        "{%0,%1,%2,%3}, {%4,%5,%6,%7}, {%8,%9}, {%0,%1,%2,%3};"
        : "+f"(d0), "+f"(d1), "+f"(d2), "+f"(d3)
        : "r"(a0), "r"(a1), "r"(a2), "r"(a3), "r"(b0), "r"(b1));
}
__device__ __forceinline__ unsigned fbits(float v) { return __float_as_uint(v); }
__device__ __forceinline__ void cpa16(void* smem_dst, const void* gsrc) {
    unsigned d = (unsigned)__cvta_generic_to_shared(smem_dst);
    asm volatile("cp.async.cg.shared.global [%0], [%1], 16;"
                 :: "r"(d), "l"(gsrc) : "memory");
}

// ---------------------------------------------------------------------------
// K1: fused GEMM (3xTF32) + zero-state segment scan.
// Grid 128 = 16 b x 8 t-segments (128 t each), 256 threads (8 warps).
// NEW data path: single cp.async burst stages RAW fp32 x(128x128) and
// B(64x128) into smem (stride 132, conflict-free); tf32 hi/lo split happens
// at fragment-load time in registers. One wait, one staging sync, 16 k-steps
// straight through. Scan identical to round 9.
// ---------------------------------------------------------------------------
#define XST 132
#define K1_SMEM_BYTES ((128 * XST + 64 * XST) * 4)   // 101376 B

__global__ __launch_bounds__(256) void fused_kernel(const float* __restrict__ x,
                                                    const float* __restrict__ Bm,
                                                    const float* __restrict__ nu,
                                                    const float* __restrict__ theta,
                                                    float* __restrict__ out) {
    extern __shared__ __align__(16) float sm[];
    float* xraw = sm;                    // [t 0..127][j 0..127] stride 132
    float* braw = sm + 128 * XST;        // [h 0..63][j 0..127]  stride 132

    __shared__ float Vr_s[4 * 64], Vi_s[4 * 64];
    __shared__ float Wr_s[4 * 64], Wi_s[4 * 64];

    const int tid  = threadIdx.x;
    const int lane = tid & 31;
    const int wid  = tid >> 5;
    const int wt   = wid >> 1;          // 0..3 -> 32 t
    const int wh   = wid & 1;           // 0..1 -> 32 h
    const int b    = blockIdx.x >> 3;
    const int ts   = blockIdx.x & 7;
    const int t0   = ts * 128;
    const int lr   = lane >> 2;         // 0..7
    const int lc   = lane & 3;          // 0..3

    // ---- Stage raw x and B via cp.async (16B chunks) ----
    // x: 128 rows x 32 chunks = 4096 -> 16 per thread
#pragma unroll
    for (int i = 0; i < 16; ++i) {
        int f  = tid + 256 * i;
        int t  = f >> 5;
        int jq = f & 31;
        cpa16(&xraw[t * XST + jq * 4], x + ((size_t)(b * TT + t0 + t) * JJ + jq * 4));
    }
    // B: 64 rows x 32 chunks = 2048 -> 8 per thread
#pragma unroll
    for (int i = 0; i < 8; ++i) {
        int f  = tid + 256 * i;
        int h  = f >> 5;
        int jq = f & 31;
        cpa16(&braw[h * XST + jq * 4], Bm + (size_t)h * JJ + jq * 4);
    }
    asm volatile("cp.async.commit_group;");
    asm volatile("cp.async.wait_group 0;" ::: "memory");
    __syncthreads();

    float acc[2][4][4];
#pragma unroll
    for (int m = 0; m < 2; ++m)
#pragma unroll
        for (int n = 0; n < 4; ++n)
#pragma unroll
            for (int q = 0; q < 4; ++q) acc[m][n][q] = 0.f;

    // ---- 16 k-steps; tf32 split at fragment load ----
#pragma unroll 4
    for (int ks = 0; ks < 16; ++ks) {
        const int j0 = ks * 8 + lc;
        // A fragments (2 m-tiles): raw loads then hi/lo split
        unsigned ah[2][4], al[2][4];
#pragma unroll
        for (int m = 0; m < 2; ++m) {
            int r0 = (wt * 32 + m * 16 + lr) * XST + j0;
            float a0 = xraw[r0];
            float a1 = xraw[r0 + 8 * XST];
            float a2 = xraw[r0 + 4];
            float a3 = xraw[r0 + 8 * XST + 4];
            ah[m][0] = tf32bits(a0); al[m][0] = fbits(a0 - __uint_as_float(ah[m][0]));
            ah[m][1] = tf32bits(a1); al[m][1] = fbits(a1 - __uint_as_float(ah[m][1]));
            ah[m][2] = tf32bits(a2); al[m][2] = fbits(a2 - __uint_as_float(ah[m][2]));
            ah[m][3] = tf32bits(a3); al[m][3] = fbits(a3 - __uint_as_float(ah[m][3]));
        }
#pragma unroll
        for (int n = 0; n < 4; ++n) {
            int rb = (wh * 32 + n * 8 + lr) * XST + j0;
            float b0 = braw[rb];
            float b1 = braw[rb + 4];
            unsigned bh0 = tf32bits(b0), bl0 = fbits(b0 - __uint_as_float(bh0));
            unsigned bh1 = tf32bits(b1), bl1 = fbits(b1 - __uint_as_float(bh1));
#pragma unroll
            for (int m = 0; m < 2; ++m) {
                mma_tf32(acc[m][n][0], acc[m][n][1], acc[m][n][2], acc[m][n][3],
                         ah[m][0], ah[m][1], ah[m][2], ah[m][3], bh0, bh1);
                mma_tf32(acc[m][n][0], acc[m][n][1], acc[m][n][2], acc[m][n][3],
                         ah[m][0], ah[m][1], ah[m][2], ah[m][3], bl0, bl1);
                mma_tf32(acc[m][n][0], acc[m][n][1], acc[m][n][2], acc[m][n][3],
                         al[m][0], al[m][1], al[m][2], al[m][3], bh0, bh1);
            }
        }
    }
    __syncthreads();

    // Stage D = Bx into smem as [t][h], stride 65 (aliases staging region).
    float* sD = sm;   // 128 * 65 floats
#pragma unroll
    for (int m = 0; m < 2; ++m)
#pragma unroll
        for (int n = 0; n < 4; ++n) {
            int tr = wt * 32 + m * 16 + lr;
            int hc = wh * 32 + n * 8 + 2 * lc;
            sD[tr * 65 + hc]           = acc[m][n][0];
            sD[tr * 65 + hc + 1]       = acc[m][n][1];
            sD[(tr + 8) * 65 + hc]     = acc[m][n][2];
            sD[(tr + 8) * 65 + hc + 1] = acc[m][n][3];
        }
    __syncthreads();

    // ---- Segment-local scan (zero initial state) ----
    const int h = tid & 63;
    const int c = tid >> 6;             // 0..3: 32-step chunk

    const float mag = expf(-expf(nu[h]));
    float sn, cs;
    sincosf(theta[h], &sn, &cs);
    const float Lr = mag * cs;
    const float Li = mag * sn;

    float u[32];
#pragma unroll
    for (int k = 0; k < 32; ++k) u[k] = sD[(c * 32 + k) * 65 + h];

    // Phase A: local chunk scan from zero -> chunk value V
    float yr = 0.f, yi = 0.f;
#pragma unroll
    for (int k = 0; k < 32; ++k) {
        float nyr = fmaf(Lr, yr, fmaf(-Li, yi, u[k]));
        float nyi = fmaf(Lr, yi, Li * yr);
        yr = nyr; yi = nyi;
    }
    Vr_s[c * 64 + h] = yr;
    Vi_s[c * 64 + h] = yi;
    __syncthreads();

    // Combine (tid<64): P = lam^32; chunk prefixes + segment carry -> g_C.
    if (tid < 64) {
        float Pr = Lr, Pi = Li;
#pragma unroll
        for (int s = 0; s < 5; ++s) {
            float nr = Pr * Pr - Pi * Pi;
            float ni = 2.f * Pr * Pi;
            Pr = nr; Pi = ni;
        }
        float wr = 0.f, wi = 0.f;
        Wr_s[h] = 0.f; Wi_s[h] = 0.f;
#pragma unroll
        for (int cc = 1; cc < 4; ++cc) {
            float vr = Vr_s[(cc - 1) * 64 + h];
            float vi = Vi_s[(cc - 1) * 64 + h];
            float nwr = vr + (Pr * wr - Pi * wi);
            float nwi = vi + (Pr * wi + Pi * wr);
            wr = nwr; wi = nwi;
            Wr_s[cc * 64 + h] = wr;
            Wi_s[cc * 64 + h] = wi;
        }
        float vr = Vr_s[3 * 64 + h];
        float vi = Vi_s[3 * 64 + h];
        float Cr = vr + (Pr * wr - Pi * wi);
        float Ci = vi + (Pr * wi + Pi * wr);
        g_C[(b * 8 + ts) * 64 + h] = make_float2(Cr, Ci);
    }
    __syncthreads();

    // Phase C: zero-state outputs (fixup adds the cross-segment correction).
    yr = Wr_s[c * 64 + h];
    yi = Wi_s[c * 64 + h];
    float* op = out + (b * TT + t0 + c * 32) * (2 * HH) + h;
#pragma unroll
    for (int k = 0; k < 32; ++k) {
        float nyr = fmaf(Lr, yr, fmaf(-Li, yi, u[k]));
        float nyi = fmaf(Lr, yi, Li * yr);
        yr = nyr; yi = nyi;
        op[k * 128]      = yr;   // re at [b,t,h]
        op[k * 128 + 64] = yi;   // im at [b,t,H+h]
    }
}

// ---------------------------------------------------------------------------
// Prep: lam^k table + incoming states S (one thread per item, ONCE).
// ---------------------------------------------------------------------------
__global__ __launch_bounds__(128) void prep_kernel(const float* __restrict__ nu,
                                                   const float* __restrict__ theta) {
    const int gid = blockIdx.x * 128 + threadIdx.x;   // 0..8191
    const int h   = gid & 63;
    const int kk  = (gid >> 6) + 1;                   // 1..128

    const float enu = expf(nu[h]);
    const float th  = theta[h];

    {
        float m = expf(-(float)kk * enu);
        float s, c;
        sincosf((float)kk * th, &s, &c);
        g_L[(kk - 1) * 64 + h] = make_float2(m * c, m * s);
    }

    const int b   = gid >> 9;
    const int seg = (gid >> 6) & 7;
    float mq = expf(-128.f * enu);
    float sq, cq;
    sincosf(128.f * th, &sq, &cq);
    const float Qr = mq * cq, Qi = mq * sq;
    float Sr = 1.f, Si = 0.f;
    for (int g = 0; g < seg; ++g) {
        float2 cg = g_C[(b * 8 + g) * 64 + h];
        float nr = Qr * Sr - Qi * Si + cg.x;
        float ni = Qr * Si + Qi * Sr + cg.y;
        Sr = nr; Si = ni;
    }
    g_S[(b * 8 + seg) * 64 + h] = make_float2(Sr, Si);
}

// ---------------------------------------------------------------------------
// Fixup: out[b,t,h] += lam_h^(tl+1) * S(b,seg,h).  Chain-free table loads.
// ---------------------------------------------------------------------------
__global__ __launch_bounds__(256) void fixup_kernel(float* __restrict__ out) {
    const int tid = threadIdx.x;
    const int bx  = blockIdx.x;         // 0..255
    const int b   = bx >> 4;
    const int tb  = bx & 15;
    const int tt  = tid >> 4;
    const int hq  = tid & 15;
    const int h0  = hq * 4;
    const int t0  = tb * 64 + tt * 4;
    const int seg = t0 >> 7;

    const float4* Sp = reinterpret_cast<const float4*>(&g_S[(b * 8 + seg) * 64 + h0]);
    float4 s01 = Sp[0], s23 = Sp[1];
    const float Sr[4] = {s01.x, s01.z, s23.x, s23.z};
    const float Si[4] = {s01.y, s01.w, s23.y, s23.w};

#pragma unroll
    for (int i = 0; i < 4; ++i) {
        const int t = t0 + i;
        const int k = (t & 127) + 1;
        const float4* Lp = reinterpret_cast<const float4*>(&g_L[(k - 1) * 64 + h0]);
        float4 l01 = Lp[0], l23 = Lp[1];
        float lkr[4] = {l01.x, l01.z, l23.x, l23.z};
        float lki[4] = {l01.y, l01.w, l23.y, l23.w};

        float* p = out + (b * TT + t) * (2 * HH) + h0;
        float4 re = *reinterpret_cast<float4*>(p);
        float4 im = *reinterpret_cast<float4*>(p + 64);
        re.x += lkr[0] * Sr[0] - lki[0] * Si[0];
        re.y += lkr[1] * Sr[1] - lki[1] * Si[1];
        re.z += lkr[2] * Sr[2] - lki[2] * Si[2];
        re.w += lkr[3] * Sr[3] - lki[3] * Si[3];
        im.x += lkr[0] * Si[0] + lki[0] * Sr[0];
        im.y += lkr[1] * Si[1] + lki[1] * Sr[1];
        im.z += lkr[2] * Si[2] + lki[2] * Sr[2];
        im.w += lkr[3] * Si[3] + lki[3] * Sr[3];
        *reinterpret_cast<float4*>(p)      = re;
        *reinterpret_cast<float4*>(p + 64) = im;
    }
}

// ---------------------------------------------------------------------------
extern "C" void kernel_launch(void* const* d_in, const int* in_sizes, int n_in,
                              void* d_out, int out_size) {
    const float* x     = (const float*)d_in[0];   // [16,1024,128]
    const float* Bm    = (const float*)d_in[1];   // [64,128]
    const float* nu    = (const float*)d_in[2];   // [64]
    const float* theta = (const float*)d_in[3];   // [64]
    float* out = (float*)d_out;                   // [16,1024,128]

    cudaFuncSetAttribute(fused_kernel,
                         cudaFuncAttributeMaxDynamicSharedMemorySize,
                         K1_SMEM_BYTES);
    fused_kernel<<<128, 256, K1_SMEM_BYTES>>>(x, Bm, nu, theta, out);
    prep_kernel<<<64, 128>>>(nu, theta);
    fixup_kernel<<<256, 256>>>(out);
}